// round 10
// baseline (speedup 1.0000x reference)
#include <cuda_runtime.h>
#include <cuda_bf16.h>
#include <cstdint>

constexpr int B    = 32;
constexpr int H    = 1024;
constexpr int MEL  = 128;
constexpr int TENC = 512;
constexpr int TMEL = 400;
constexpr int H4   = H / 4;

constexpr size_t OFF_GATE = (size_t)B * TMEL * MEL;
constexpr size_t OFF_MASK = OFF_GATE + (size_t)B * TMEL;

// ---------------- device scratch (no allocations allowed) -------------------
__device__ float g_WT[(size_t)H * H];       // W_attn^T: g_WT[c*H+j] = W_attn[j*H+c]
__device__ float g_h0[2][B * H];
__device__ float g_h1[2][B * H];
__device__ float g_decin[B * MEL];
__device__ float g_v[B * H];
__device__ float g_scores[B * TENC];
__device__ float g_ctx[B * H];
__device__ float g_co[B * H];

// barriers
__device__ unsigned g_bar_arrive = 0;
__device__ volatile unsigned g_bar_gen = 0;
__device__ volatile unsigned g_arr[152 * 8];
__device__ volatile unsigned g_release;

// ---------------- helpers ----------------------------------------------------
__device__ __forceinline__ float wsum(float v) {
    v += __shfl_xor_sync(0xffffffffu, v, 16);
    v += __shfl_xor_sync(0xffffffffu, v, 8);
    v += __shfl_xor_sync(0xffffffffu, v, 4);
    v += __shfl_xor_sync(0xffffffffu, v, 2);
    v += __shfl_xor_sync(0xffffffffu, v, 1);
    return v;
}
__device__ __forceinline__ float wmax(float v) {
    v = fmaxf(v, __shfl_xor_sync(0xffffffffu, v, 16));
    v = fmaxf(v, __shfl_xor_sync(0xffffffffu, v, 8));
    v = fmaxf(v, __shfl_xor_sync(0xffffffffu, v, 4));
    v = fmaxf(v, __shfl_xor_sync(0xffffffffu, v, 2));
    v = fmaxf(v, __shfl_xor_sync(0xffffffffu, v, 1));
    return v;
}
__device__ __forceinline__ float dot4(float4 a, float4 b, float acc) {
    acc = fmaf(a.x, b.x, acc);
    acc = fmaf(a.y, b.y, acc);
    acc = fmaf(a.z, b.z, acc);
    acc = fmaf(a.w, b.w, acc);
    return acc;
}
__device__ __forceinline__ float sigmoidf_(float x) { return 1.f / (1.f + expf(-x)); }

// legacy atomic barrier (re-launch safe); used once after init
__device__ __forceinline__ void abar(int nblk) {
    __syncthreads();
    if (threadIdx.x == 0) {
        __threadfence();
        unsigned gen = g_bar_gen;
        if (atomicAdd(&g_bar_arrive, 1u) == (unsigned)nblk - 1u) {
            g_bar_arrive = 0;
            __threadfence();
            g_bar_gen = gen + 1u;
        } else {
            while (g_bar_gen == gen) { __nanosleep(64); }
        }
        __threadfence();
    }
    __syncthreads();
}

// grid barrier: per-block arrive slots, block 0 scans, all others poll one
// broadcast release word with backoff.
__device__ __forceinline__ void sbar(int nblk, int bx, unsigned gen) {
    __syncthreads();
    if (threadIdx.x == 0) { __threadfence(); g_arr[bx * 8] = gen; }
    if (bx == 0) {
        if (threadIdx.x < 32) {
            for (;;) {
                bool ok = true;
                for (int i = threadIdx.x; i < nblk; i += 32)
                    ok &= (g_arr[i * 8] >= gen);
                if (__all_sync(0xffffffffu, ok)) break;
                __nanosleep(32);
            }
            if (threadIdx.x == 0) { __threadfence(); g_release = gen; }
        }
    } else if (threadIdx.x == 0) {
        while (g_release < gen) { __nanosleep(64); }
        __threadfence();
    }
    __syncthreads();
}

// ---------------- merged GRU cell, software-pipelined ------------------------
// One job = (column j, 8 batches). Weight loads for iteration k+1 are issued
// before the FMAs of iteration k; activations are L1-resident (64 KB/block).
__device__ __forceinline__ void gru_job(
    int j, int b0, int lane,
    const float* __restrict__ x, int XD,
    const float* __restrict__ hprev, float* __restrict__ hnew,
    const float* __restrict__ Wih, const float* __restrict__ Whh,
    const float* __restrict__ bih, const float* __restrict__ bhh)
{
    const int XD4 = XD >> 2;
    float ar[8], az[8], ani[8], anh[8];
#pragma unroll
    for (int i = 0; i < 8; ++i) { ar[i] = 0.f; az[i] = 0.f; ani[i] = 0.f; anh[i] = 0.f; }

    {   // input side: ir, iz, in
        const float4* wr = reinterpret_cast<const float4*>(Wih + (size_t)j * XD);
        const float4* wz = reinterpret_cast<const float4*>(Wih + (size_t)(H + j) * XD);
        const float4* wn = reinterpret_cast<const float4*>(Wih + (size_t)(2 * H + j) * XD);
        const float4* x4 = reinterpret_cast<const float4*>(x);
        float4 r4 = wr[lane], z4 = wz[lane], n4 = wn[lane];
        for (int k = lane; k < XD4; k += 32) {
            float4 r4n = r4, z4n = z4, n4n = n4;
            const int kn = k + 32;
            if (kn < XD4) { r4n = wr[kn]; z4n = wz[kn]; n4n = wn[kn]; }
            const float4* xk = x4 + k;
#pragma unroll
            for (int bb = 0; bb < 8; ++bb) {
                float4 xv = xk[(size_t)(b0 + bb) * XD4];
                ar[bb]  = dot4(r4, xv, ar[bb]);
                az[bb]  = dot4(z4, xv, az[bb]);
                ani[bb] = dot4(n4, xv, ani[bb]);
            }
            r4 = r4n; z4 = z4n; n4 = n4n;
        }
    }
    {   // hidden side: hr, hz, hn
        const float4* wr = reinterpret_cast<const float4*>(Whh + (size_t)j * H);
        const float4* wz = reinterpret_cast<const float4*>(Whh + (size_t)(H + j) * H);
        const float4* wn = reinterpret_cast<const float4*>(Whh + (size_t)(2 * H + j) * H);
        const float4* h4 = reinterpret_cast<const float4*>(hprev);
        float4 r4 = wr[lane], z4 = wz[lane], n4 = wn[lane];
        for (int k = lane; k < H4; k += 32) {
            float4 r4n = r4, z4n = z4, n4n = n4;
            const int kn = k + 32;
            if (kn < H4) { r4n = wr[kn]; z4n = wz[kn]; n4n = wn[kn]; }
            const float4* hk = h4 + k;
#pragma unroll
            for (int bb = 0; bb < 8; ++bb) {
                float4 hv = hk[(size_t)(b0 + bb) * H4];
                ar[bb]  = dot4(r4, hv, ar[bb]);
                az[bb]  = dot4(z4, hv, az[bb]);
                anh[bb] = dot4(n4, hv, anh[bb]);
            }
            r4 = r4n; z4 = z4n; n4 = n4n;
        }
    }
    const float br  = bih[j] + bhh[j];
    const float bz  = bih[H + j] + bhh[H + j];
    const float bni = bih[2 * H + j];
    const float bnh = bhh[2 * H + j];
#pragma unroll
    for (int bb = 0; bb < 8; ++bb) {
        float r  = wsum(ar[bb]);
        float z  = wsum(az[bb]);
        float ni = wsum(ani[bb]);
        float nh = wsum(anh[bb]);
        if (lane == bb) {
            float rr = sigmoidf_(r + br);
            float zz = sigmoidf_(z + bz);
            float nn = tanhf(ni + bni + rr * (nh + bnh));
            const int idx = (b0 + bb) * H + j;
            hnew[idx] = (1.f - zz) * nn + zz * hprev[idx];
        }
    }
}

// ---------------- main persistent kernel -------------------------------------
__global__ void __launch_bounds__(512, 1)
decoder_kernel(const float* __restrict__ enc_hidden,
               const float* __restrict__ enc_out,
               const int*   __restrict__ lens,
               const float* __restrict__ W_attn, const float* __restrict__ b_attn,
               const float* __restrict__ Wih0, const float* __restrict__ Whh0,
               const float* __restrict__ bih0, const float* __restrict__ bhh0,
               const float* __restrict__ Wih1, const float* __restrict__ Whh1,
               const float* __restrict__ bih1, const float* __restrict__ bhh1,
               const float* __restrict__ Wc,   const float* __restrict__ bc,
               const float* __restrict__ Wp,   const float* __restrict__ bp,
               const float* __restrict__ Wg,   const float* __restrict__ bg,
               float* __restrict__ out, int nblk) {
    const int tid  = threadIdx.x;
    const int lane = tid & 31;
    const int wid  = tid >> 5;
    const int bx   = blockIdx.x;
    // batch-quarter mapping: block handles ONE batch quarter (8 batches) ->
    // activation working set 64 KB, L1-resident, shared by all 16 warps.
    const int q    = bx & 3;                 // quarter (nblk divisible by 4)
    const int bq   = bx >> 2;                // block index within quarter
    const int nbq  = nblk >> 2;              // blocks per quarter
    const int wq   = bq * 16 + wid;          // warp index within quarter
    const int NWQ  = nbq * 16;               // warps per quarter
    const int b0q  = q * 8;
    const int gtid = bx * blockDim.x + tid;
    const int gsz  = nblk * blockDim.x;

    // ================= init =================
    for (int i = gtid; i < H * H; i += gsz) {
        int c = i >> 10, j = i & (H - 1);
        g_WT[i] = W_attn[(size_t)j * H + c];
    }
    for (int i = gtid; i < B * H; i += gsz) {
        g_h0[0][i] = enc_hidden[i];
        g_h1[0][i] = enc_hidden[B * H + i];
    }
    for (int i = gtid; i < B * MEL; i += gsz) g_decin[i] = 0.f;
    for (int i = gtid; i < B * TMEL; i += gsz) {
        int b = i / TMEL, t = i - b * TMEL;
        out[OFF_MASK + i] = (t > lens[b]) ? 1.f : 0.f;
    }
    for (int i = gtid; i < 152 * 8; i += gsz) g_arr[i] = 0u;
    if (gtid == 0) g_release = 0u;
    abar(nblk);

    unsigned gen = 0;

    // ================= 400 autoregressive steps =================
    for (int step = 0; step < TMEL; ++step) {
        const int cur = step & 1, nxt = cur ^ 1;

        // ---- GRU layer 0 ----
        for (int j = wq; j < H; j += NWQ)
            gru_job(j, b0q, lane, g_decin, MEL, g_h0[cur], g_h0[nxt],
                    Wih0, Whh0, bih0, bhh0);
        sbar(nblk, bx, ++gen);

        // ---- GRU layer 1 ----
        for (int j = wq; j < H; j += NWQ)
            gru_job(j, b0q, lane, g_h0[nxt], H, g_h1[cur], g_h1[nxt],
                    Wih1, Whh1, bih1, bhh1);
        sbar(nblk, bx, ++gen);

        const float* h1n = g_h1[nxt];

        // ---- Pv: v[b,c] = sum_j h1[b,j] * W_attn[j,c]  (bias drops in softmax) ----
        for (int c = wq; c < H; c += NWQ) {
            float acc[8];
#pragma unroll
            for (int i = 0; i < 8; ++i) acc[i] = 0.f;
            const float4* wk = reinterpret_cast<const float4*>(g_WT + (size_t)c * H);
            const float4* h4 = reinterpret_cast<const float4*>(h1n);
            float4 wv = wk[lane];
            for (int k = lane; k < H4; k += 32) {
                float4 wvn = wv;
                const int kn = k + 32;
                if (kn < H4) wvn = wk[kn];
                const float4* hk = h4 + k;
#pragma unroll
                for (int bb = 0; bb < 8; ++bb)
                    acc[bb] = dot4(wv, hk[(size_t)(b0q + bb) * H4], acc[bb]);
                wv = wvn;
            }
#pragma unroll
            for (int bb = 0; bb < 8; ++bb) {
                float s = wsum(acc[bb]);
                if (lane == bb) g_v[(b0q + bb) * H + c] = s;
            }
        }
        sbar(nblk, bx, ++gen);

        // ---- P3: scores[b,t] = v[b,:] . enc_out[b,t,:]  (512 jobs/quarter) ----
        for (int job = wq; job < 512; job += NWQ) {
            const int b  = b0q + (job >> 6);
            const int t0 = (job & 63) * 8;
            float acc[8];
#pragma unroll
            for (int i = 0; i < 8; ++i) acc[i] = 0.f;
            const float4* vb = reinterpret_cast<const float4*>(g_v + (size_t)b * H);
            const float4* Eb = reinterpret_cast<const float4*>(
                enc_out + ((size_t)b * TENC + t0) * H);
            float4 vv = vb[lane];
            for (int k = lane; k < H4; k += 32) {
                float4 vvn = vv;
                const int kn = k + 32;
                if (kn < H4) vvn = vb[kn];
#pragma unroll
                for (int t = 0; t < 8; ++t) {
                    float4 ev = Eb[(size_t)t * H4 + k];
                    acc[t] = fmaf(vv.x, ev.x, fmaf(vv.y, ev.y,
                             fmaf(vv.z, ev.z, fmaf(vv.w, ev.w, acc[t]))));
                }
                vv = vvn;
            }
#pragma unroll
            for (int t = 0; t < 8; ++t) {
                float s = wsum(acc[t]);
                if (lane == t) g_scores[b * TENC + t0 + t] = s;
            }
        }
        sbar(nblk, bx, ++gen);

        // ---- P4: softmax (per-warp) + context (256 jobs/quarter) ----
        for (int job = wq; job < 256; job += NWQ) {
            const int b  = b0q + (job >> 5);
            const int hg = (job & 31) * 32;
            const float* srow = g_scores + b * TENC;
            float sc[16];
            float mx = -1e30f;
#pragma unroll
            for (int i = 0; i < 16; ++i) {
                sc[i] = srow[i * 32 + lane];
                mx = fmaxf(mx, sc[i]);
            }
            mx = wmax(mx);
            float sm = 0.f;
#pragma unroll
            for (int i = 0; i < 16; ++i) { sc[i] = expf(sc[i] - mx); sm += sc[i]; }
            sm = wsum(sm);
            const float inv = 1.f / sm;

            float acc0 = 0.f, acc1 = 0.f;
            const float* ep = enc_out + (size_t)b * TENC * H + hg + lane;
#pragma unroll
            for (int i = 0; i < 8; ++i) {
                float pv0 = sc[i] * inv;
                float pv1 = sc[i + 8] * inv;
#pragma unroll 8
                for (int tt = 0; tt < 32; ++tt) {
                    float p0 = __shfl_sync(0xffffffffu, pv0, tt);
                    float p1 = __shfl_sync(0xffffffffu, pv1, tt);
                    float e0 = ep[(size_t)(i * 32 + tt) * H];
                    float e1 = ep[(size_t)((i + 8) * 32 + tt) * H];
                    acc0 = fmaf(p0, e0, acc0);
                    acc1 = fmaf(p1, e1, acc1);
                }
            }
            g_ctx[(size_t)b * H + hg + lane] = acc0 + acc1;
        }
        sbar(nblk, bx, ++gen);

        // ---- P5: co = tanh([h1; ctx] @ Wc^T + bc) ----
        for (int j = wq; j < H; j += NWQ) {
            float acc[8];
#pragma unroll
            for (int i = 0; i < 8; ++i) acc[i] = 0.f;
            const float4* w1 = reinterpret_cast<const float4*>(Wc + (size_t)j * 2 * H);
            const float4* w2 = w1 + H4;
            const float4* h4 = reinterpret_cast<const float4*>(h1n);
            const float4* c4 = reinterpret_cast<const float4*>(g_ctx);
            float4 wv = w1[lane];
            for (int k = lane; k < H4; k += 32) {
                float4 wvn = wv;
                const int kn = k + 32;
                if (kn < H4) wvn = w1[kn];
                const float4* hk = h4 + k;
#pragma unroll
                for (int bb = 0; bb < 8; ++bb)
                    acc[bb] = dot4(wv, hk[(size_t)(b0q + bb) * H4], acc[bb]);
                wv = wvn;
            }
            wv = w2[lane];
            for (int k = lane; k < H4; k += 32) {
                float4 wvn = wv;
                const int kn = k + 32;
                if (kn < H4) wvn = w2[kn];
                const float4* ck = c4 + k;
#pragma unroll
                for (int bb = 0; bb < 8; ++bb)
                    acc[bb] = dot4(wv, ck[(size_t)(b0q + bb) * H4], acc[bb]);
                wv = wvn;
            }
            const float bcv = bc[j];
#pragma unroll
            for (int bb = 0; bb < 8; ++bb) {
                float s = wsum(acc[bb]);
                if (lane == bb) g_co[(b0q + bb) * H + j] = tanhf(s + bcv);
            }
        }
        sbar(nblk, bx, ++gen);

        // ---- P6: mel + gate projections, outputs, next decin (129 jobs/quarter) ----
        for (int c = wq; c <= MEL; c += NWQ) {
            float acc[8];
#pragma unroll
            for (int i = 0; i < 8; ++i) acc[i] = 0.f;
            const float4* wp = reinterpret_cast<const float4*>(
                (c < MEL) ? (Wp + (size_t)c * H) : Wg);
            const float4* co4 = reinterpret_cast<const float4*>(g_co);
            float4 wv = wp[lane];
            for (int k = lane; k < H4; k += 32) {
                float4 wvn = wv;
                const int kn = k + 32;
                if (kn < H4) wvn = wp[kn];
                const float4* ck = co4 + k;
#pragma unroll
                for (int bb = 0; bb < 8; ++bb)
                    acc[bb] = dot4(wv, ck[(size_t)(b0q + bb) * H4], acc[bb]);
                wv = wvn;
            }
            const float bias = (c < MEL) ? bp[c] : bg[0];
#pragma unroll
            for (int bb = 0; bb < 8; ++bb) {
                float s = wsum(acc[bb]);
                if (lane == bb) {
                    const int b = b0q + bb;
                    const bool msk = step > lens[b];
                    if (c < MEL) {
                        const float val = s + bias;
                        g_decin[b * MEL + c] = val;
                        out[((size_t)b * TMEL + step) * MEL + c] = msk ? 0.f : val;
                    } else {
                        out[OFF_GATE + (size_t)b * TMEL + step] = msk ? 1000.f : (s + bias);
                    }
                }
            }
        }
        sbar(nblk, bx, ++gen);
    }
}

// ---------------- host launch -------------------------------------------------
extern "C" void kernel_launch(void* const* d_in, const int* in_sizes, int n_in,
                              void* d_out, int out_size) {
    (void)in_sizes; (void)n_in; (void)out_size;
    int dev = 0;
    cudaGetDevice(&dev);
    int sms = 0;
    cudaDeviceGetAttribute(&sms, cudaDevAttrMultiProcessorCount, dev);
    if (sms <= 0) sms = 148;
    if (sms > 152) sms = 152;
    sms &= ~3;                                // multiple of 4 for quarter mapping

    decoder_kernel<<<sms, 512>>>(
        (const float*)d_in[0],   // encoder_hidden [4,B,H]
        (const float*)d_in[1],   // encoder_outputs [B,TENC,H]
        (const int*)d_in[3],     // mel_spec_lens [B]   (d_in[2] = y, unused)
        (const float*)d_in[4],  (const float*)d_in[5],    // W_attn, b_attn
        (const float*)d_in[6],  (const float*)d_in[7],    // W_ih0, W_hh0
        (const float*)d_in[8],  (const float*)d_in[9],    // b_ih0, b_hh0
        (const float*)d_in[10], (const float*)d_in[11],   // W_ih1, W_hh1
        (const float*)d_in[12], (const float*)d_in[13],   // b_ih1, b_hh1
        (const float*)d_in[14], (const float*)d_in[15],   // Wc, bc
        (const float*)d_in[16], (const float*)d_in[17],   // Wp, bp
        (const float*)d_in[18], (const float*)d_in[19],   // Wg, bg
        (float*)d_out, sms);
}

// round 11
// speedup vs baseline: 1.2164x; 1.2164x over previous
#include <cuda_runtime.h>
#include <cuda_bf16.h>
#include <cstdint>

constexpr int B    = 32;
constexpr int H    = 1024;
constexpr int MEL  = 128;
constexpr int TENC = 512;
constexpr int TMEL = 400;
constexpr int H4   = H / 4;

constexpr size_t OFF_GATE = (size_t)B * TMEL * MEL;
constexpr size_t OFF_MASK = OFF_GATE + (size_t)B * TMEL;

// ---------------- device scratch (no allocations allowed) -------------------
__device__ float g_WT[(size_t)H * H];       // W_attn^T: g_WT[c*H+j] = W_attn[j*H+c]
__device__ float g_h0[2][B * H];
__device__ float g_h1[2][B * H];
__device__ float g_decin[B * MEL];
__device__ float g_v[B * H];
__device__ float g_scores[B * TENC];
__device__ float g_ctx[B * H];
__device__ float g_co[B * H];

// barriers
__device__ unsigned g_bar_arrive = 0;
__device__ volatile unsigned g_bar_gen = 0;
__device__ volatile unsigned g_arr[152 * 8];
__device__ volatile unsigned g_release;

// ---------------- helpers ----------------------------------------------------
__device__ __forceinline__ float wsum(float v) {
    v += __shfl_xor_sync(0xffffffffu, v, 16);
    v += __shfl_xor_sync(0xffffffffu, v, 8);
    v += __shfl_xor_sync(0xffffffffu, v, 4);
    v += __shfl_xor_sync(0xffffffffu, v, 2);
    v += __shfl_xor_sync(0xffffffffu, v, 1);
    return v;
}
__device__ __forceinline__ float wmax(float v) {
    v = fmaxf(v, __shfl_xor_sync(0xffffffffu, v, 16));
    v = fmaxf(v, __shfl_xor_sync(0xffffffffu, v, 8));
    v = fmaxf(v, __shfl_xor_sync(0xffffffffu, v, 4));
    v = fmaxf(v, __shfl_xor_sync(0xffffffffu, v, 2));
    v = fmaxf(v, __shfl_xor_sync(0xffffffffu, v, 1));
    return v;
}
__device__ __forceinline__ float dot4(float4 a, float4 b, float acc) {
    acc = fmaf(a.x, b.x, acc);
    acc = fmaf(a.y, b.y, acc);
    acc = fmaf(a.z, b.z, acc);
    acc = fmaf(a.w, b.w, acc);
    return acc;
}
__device__ __forceinline__ float sigmoidf_(float x) { return 1.f / (1.f + expf(-x)); }

// legacy atomic barrier (re-launch safe); used once after init
__device__ __forceinline__ void abar(int nblk) {
    __syncthreads();
    if (threadIdx.x == 0) {
        __threadfence();
        unsigned gen = g_bar_gen;
        if (atomicAdd(&g_bar_arrive, 1u) == (unsigned)nblk - 1u) {
            g_bar_arrive = 0;
            __threadfence();
            g_bar_gen = gen + 1u;
        } else {
            while (g_bar_gen == gen) { __nanosleep(64); }
        }
        __threadfence();
    }
    __syncthreads();
}

// grid barrier: per-block arrive slots, block 0 scans, all others poll one
// broadcast release word with backoff.
__device__ __forceinline__ void sbar(int nblk, int bx, unsigned gen) {
    __syncthreads();
    if (threadIdx.x == 0) { __threadfence(); g_arr[bx * 8] = gen; }
    if (bx == 0) {
        if (threadIdx.x < 32) {
            for (;;) {
                bool ok = true;
                for (int i = threadIdx.x; i < nblk; i += 32)
                    ok &= (g_arr[i * 8] >= gen);
                if (__all_sync(0xffffffffu, ok)) break;
                __nanosleep(32);
            }
            if (threadIdx.x == 0) { __threadfence(); g_release = gen; }
        }
    } else if (threadIdx.x == 0) {
        while (g_release < gen) { __nanosleep(64); }
        __threadfence();
    }
    __syncthreads();
}

// stage a half-batch activation slab into shared memory (coalesced float4)
__device__ __forceinline__ void stage(float4* dst, const float* src, int n4, int tid) {
    const float4* s = reinterpret_cast<const float4*>(src);
    for (int i = tid; i < n4; i += 512) dst[i] = s[i];
}

// 3-row dot vs 8 batches (acts in smem), weight prefetch depth 2.
// actb = smem base already offset to batch-group; bstride4 = per-batch stride (f4).
__device__ __forceinline__ void dot3(
    const float4* __restrict__ w0, const float4* __restrict__ w1,
    const float4* __restrict__ w2,
    const float4* __restrict__ actb, int bstride4, int nIt, int lane,
    float A0[8], float A1[8], float A2[8])
{
    float4 c0 = w0[lane], c1 = w1[lane], c2 = w2[lane];
    float4 n0 = c0, n1 = c1, n2 = c2;
    if (nIt > 1) { n0 = w0[lane + 32]; n1 = w1[lane + 32]; n2 = w2[lane + 32]; }
    for (int i = 0; i < nIt; ++i) {
        float4 p0 = n0, p1 = n1, p2 = n2;
        if (i + 2 < nIt) {
            p0 = w0[lane + (i + 2) * 32];
            p1 = w1[lane + (i + 2) * 32];
            p2 = w2[lane + (i + 2) * 32];
        }
        const float4* a = actb + i * 32 + lane;
#pragma unroll
        for (int bb = 0; bb < 8; ++bb) {
            float4 av = a[bb * bstride4];
            A0[bb] = dot4(c0, av, A0[bb]);
            A1[bb] = dot4(c1, av, A1[bb]);
            A2[bb] = dot4(c2, av, A2[bb]);
        }
        c0 = n0; c1 = n1; c2 = n2;
        n0 = p0; n1 = p1; n2 = p2;
    }
}

// 1-row dot vs 8 batches, prefetch depth 2 (acts smem or global).
__device__ __forceinline__ void dot1(
    const float4* __restrict__ w,
    const float4* __restrict__ actb, int bstride4, int nIt, int lane,
    float A[8])
{
    float4 c = w[lane];
    float4 n = c;
    if (nIt > 1) n = w[lane + 32];
    for (int i = 0; i < nIt; ++i) {
        float4 p = n;
        if (i + 2 < nIt) p = w[lane + (i + 2) * 32];
        const float4* a = actb + i * 32 + lane;
#pragma unroll
        for (int bb = 0; bb < 8; ++bb)
            A[bb] = dot4(c, a[bb * bstride4], A[bb]);
        c = n; n = p;
    }
}

// merged GRU cell: acts from smem, direct state write
__device__ __forceinline__ void gru_sm(
    int j, int bl0, int lane, int hb0,
    const float4* __restrict__ smX, int XD,
    const float4* __restrict__ smH, const float* __restrict__ smHf,
    float* __restrict__ hnew,
    const float* __restrict__ Wih, const float* __restrict__ Whh,
    const float* __restrict__ bih, const float* __restrict__ bhh)
{
    const int XD4 = XD >> 2, nItX = XD4 >> 5;
    float ar[8], az[8], ani[8], anh[8];
#pragma unroll
    for (int i = 0; i < 8; ++i) { ar[i] = 0.f; az[i] = 0.f; ani[i] = 0.f; anh[i] = 0.f; }

    dot3(reinterpret_cast<const float4*>(Wih + (size_t)j * XD),
         reinterpret_cast<const float4*>(Wih + (size_t)(H + j) * XD),
         reinterpret_cast<const float4*>(Wih + (size_t)(2 * H + j) * XD),
         smX + bl0 * XD4, XD4, nItX, lane, ar, az, ani);
    dot3(reinterpret_cast<const float4*>(Whh + (size_t)j * H),
         reinterpret_cast<const float4*>(Whh + (size_t)(H + j) * H),
         reinterpret_cast<const float4*>(Whh + (size_t)(2 * H + j) * H),
         smH + bl0 * H4, H4, 8, lane, ar, az, anh);

    const float br  = bih[j] + bhh[j];
    const float bz  = bih[H + j] + bhh[H + j];
    const float bni = bih[2 * H + j];
    const float bnh = bhh[2 * H + j];
#pragma unroll
    for (int bb = 0; bb < 8; ++bb) {
        float r  = wsum(ar[bb]);
        float z  = wsum(az[bb]);
        float ni = wsum(ani[bb]);
        float nh = wsum(anh[bb]);
        if (lane == bb) {
            float rr = sigmoidf_(r + br);
            float zz = sigmoidf_(z + bz);
            float hp = smHf[(bl0 + bb) * H + j];
            float nn = tanhf(ni + bni + rr * (nh + bnh));
            hnew[(hb0 + bl0 + bb) * H + j] = (1.f - zz) * nn + zz * hp;
        }
    }
}

// ---------------- main persistent kernel -------------------------------------
__global__ void __launch_bounds__(512, 1)
decoder_kernel(const float* __restrict__ enc_hidden,
               const float* __restrict__ enc_out,
               const int*   __restrict__ lens,
               const float* __restrict__ W_attn, const float* __restrict__ b_attn,
               const float* __restrict__ Wih0, const float* __restrict__ Whh0,
               const float* __restrict__ bih0, const float* __restrict__ bhh0,
               const float* __restrict__ Wih1, const float* __restrict__ Whh1,
               const float* __restrict__ bih1, const float* __restrict__ bhh1,
               const float* __restrict__ Wc,   const float* __restrict__ bc,
               const float* __restrict__ Wp,   const float* __restrict__ bp,
               const float* __restrict__ Wg,   const float* __restrict__ bg,
               float* __restrict__ out, int nblk) {
    extern __shared__ float4 sm4[];
    float4* smA = sm4;                 // 4096 f4 (64 KB)
    float4* smB = sm4 + 4096;          // 4096 f4 (64 KB)
    const float* smAf = reinterpret_cast<const float*>(smA);
    const float* smBf = reinterpret_cast<const float*>(smB);

    const int tid  = threadIdx.x;
    const int lane = tid & 31;
    const int wid  = tid >> 5;
    const int bx   = blockIdx.x;
    // half mapping: block owns one 16-batch half; acts staged in smem.
    const int half = bx & 1;
    const int bq   = bx >> 1;
    const int nbh  = nblk >> 1;
    const int wq   = bq * 16 + wid;     // warp index within half
    const int NWQ  = nbh * 16;          // warps per half
    const int hb0  = half * 16;         // first batch of half
    const int gtid = bx * blockDim.x + tid;
    const int gsz  = nblk * blockDim.x;

    // ================= init =================
    for (int i = gtid; i < H * H; i += gsz) {
        int c = i >> 10, j = i & (H - 1);
        g_WT[i] = W_attn[(size_t)j * H + c];
    }
    for (int i = gtid; i < B * H; i += gsz) {
        g_h0[0][i] = enc_hidden[i];
        g_h1[0][i] = enc_hidden[B * H + i];
    }
    for (int i = gtid; i < B * MEL; i += gsz) g_decin[i] = 0.f;
    for (int i = gtid; i < B * TMEL; i += gsz) {
        int b = i / TMEL, t = i - b * TMEL;
        out[OFF_MASK + i] = (t > lens[b]) ? 1.f : 0.f;
    }
    for (int i = gtid; i < 152 * 8; i += gsz) g_arr[i] = 0u;
    if (gtid == 0) g_release = 0u;
    abar(nblk);

    unsigned gen = 0;

    // ================= 400 autoregressive steps =================
    for (int step = 0; step < TMEL; ++step) {
        const int cur = step & 1, nxt = cur ^ 1;

        // ---- GRU layer 0 (x = decin in smA, h = h0[cur] in smB) ----
        stage(smA, g_decin + hb0 * MEL, 16 * MEL / 4, tid);
        stage(smB, g_h0[cur] + hb0 * H, 4096, tid);
        __syncthreads();
        for (int job = wq; job < 2048; job += NWQ)
            gru_sm(job >> 1, (job & 1) * 8, lane, hb0, smA, MEL, smB, smBf,
                   g_h0[nxt], Wih0, Whh0, bih0, bhh0);
        sbar(nblk, bx, ++gen);

        // ---- GRU layer 1 (x = h0[nxt] in smA, h = h1[cur] in smB) ----
        stage(smA, g_h0[nxt] + hb0 * H, 4096, tid);
        stage(smB, g_h1[cur] + hb0 * H, 4096, tid);
        __syncthreads();
        for (int job = wq; job < 2048; job += NWQ)
            gru_sm(job >> 1, (job & 1) * 8, lane, hb0, smA, H, smB, smBf,
                   g_h1[nxt], Wih1, Whh1, bih1, bhh1);
        sbar(nblk, bx, ++gen);

        // ---- Pv: v[b,c] = sum_j h1[b,j] * W_attn[j,c] (bias drops in softmax) ----
        stage(smA, g_h1[nxt] + hb0 * H, 4096, tid);
        __syncthreads();
        for (int job = wq; job < 2048; job += NWQ) {
            const int c   = job >> 1;
            const int bl0 = (job & 1) * 8;
            float acc[8];
#pragma unroll
            for (int i = 0; i < 8; ++i) acc[i] = 0.f;
            dot1(reinterpret_cast<const float4*>(g_WT + (size_t)c * H),
                 smA + bl0 * H4, H4, 8, lane, acc);
#pragma unroll
            for (int bb = 0; bb < 8; ++bb) {
                float s = wsum(acc[bb]);
                if (lane == bb) g_v[(hb0 + bl0 + bb) * H + c] = s;
            }
        }
        sbar(nblk, bx, ++gen);

        // ---- P3: scores[b,t] = v[b,:] . enc_out[b,t,:]  (1024 jobs/half) ----
        stage(smA, g_v + hb0 * H, 4096, tid);
        __syncthreads();
        for (int job = wq; job < 1024; job += NWQ) {
            const int bl = job >> 6;
            const int b  = hb0 + bl;
            const int t0 = (job & 63) * 8;
            float acc[8];
#pragma unroll
            for (int i = 0; i < 8; ++i) acc[i] = 0.f;
            const float4* vb = smA + bl * H4;
            const float4* Eb = reinterpret_cast<const float4*>(
                enc_out + ((size_t)b * TENC + t0) * H);
            for (int k = lane; k < H4; k += 32) {
                float4 vv = vb[k];
#pragma unroll
                for (int t = 0; t < 8; ++t) {
                    float4 ev = Eb[(size_t)t * H4 + k];
                    acc[t] = fmaf(vv.x, ev.x, fmaf(vv.y, ev.y,
                             fmaf(vv.z, ev.z, fmaf(vv.w, ev.w, acc[t]))));
                }
            }
#pragma unroll
            for (int t = 0; t < 8; ++t) {
                float s = wsum(acc[t]);
                if (lane == t) g_scores[b * TENC + t0 + t] = s;
            }
        }
        sbar(nblk, bx, ++gen);

        // ---- P4: softmax (per-warp) + context (512 jobs/half) ----
        for (int job = wq; job < 512; job += NWQ) {
            const int b  = hb0 + (job >> 5);
            const int hg = (job & 31) * 32;
            const float* srow = g_scores + b * TENC;
            float sc[16];
            float mx = -1e30f;
#pragma unroll
            for (int i = 0; i < 16; ++i) {
                sc[i] = srow[i * 32 + lane];
                mx = fmaxf(mx, sc[i]);
            }
            mx = wmax(mx);
            float sm = 0.f;
#pragma unroll
            for (int i = 0; i < 16; ++i) { sc[i] = expf(sc[i] - mx); sm += sc[i]; }
            sm = wsum(sm);
            const float inv = 1.f / sm;

            float acc0 = 0.f, acc1 = 0.f;
            const float* ep = enc_out + (size_t)b * TENC * H + hg + lane;
#pragma unroll
            for (int i = 0; i < 8; ++i) {
                float pv0 = sc[i] * inv;
                float pv1 = sc[i + 8] * inv;
#pragma unroll 8
                for (int tt = 0; tt < 32; ++tt) {
                    float p0 = __shfl_sync(0xffffffffu, pv0, tt);
                    float p1 = __shfl_sync(0xffffffffu, pv1, tt);
                    float e0 = ep[(size_t)(i * 32 + tt) * H];
                    float e1 = ep[(size_t)((i + 8) * 32 + tt) * H];
                    acc0 = fmaf(p0, e0, acc0);
                    acc1 = fmaf(p1, e1, acc1);
                }
            }
            g_ctx[(size_t)b * H + hg + lane] = acc0 + acc1;
        }
        sbar(nblk, bx, ++gen);

        // ---- P5: co = tanh([h1; ctx] @ Wc^T + bc) (h1 in smA, ctx in smB) ----
        stage(smA, g_h1[nxt] + hb0 * H, 4096, tid);
        stage(smB, g_ctx + hb0 * H, 4096, tid);
        __syncthreads();
        for (int job = wq; job < 2048; job += NWQ) {
            const int j   = job >> 1;
            const int bl0 = (job & 1) * 8;
            float acc[8];
#pragma unroll
            for (int i = 0; i < 8; ++i) acc[i] = 0.f;
            dot1(reinterpret_cast<const float4*>(Wc + (size_t)j * 2 * H),
                 smA + bl0 * H4, H4, 8, lane, acc);
            dot1(reinterpret_cast<const float4*>(Wc + (size_t)j * 2 * H) + H4,
                 smB + bl0 * H4, H4, 8, lane, acc);
            const float bcv = bc[j];
#pragma unroll
            for (int bb = 0; bb < 8; ++bb) {
                float s = wsum(acc[bb]);
                if (lane == bb) g_co[(hb0 + bl0 + bb) * H + j] = tanhf(s + bcv);
            }
        }
        sbar(nblk, bx, ++gen);

        // ---- P6: mel + gate projections (258 jobs/half, co from L2) ----
        for (int job = wq; job < 258; job += NWQ) {
            const int c   = job >> 1;
            const int bl0 = (job & 1) * 8;
            const int b0  = hb0 + bl0;
            float acc[8];
#pragma unroll
            for (int i = 0; i < 8; ++i) acc[i] = 0.f;
            const float4* wp = reinterpret_cast<const float4*>(
                (c < MEL) ? (Wp + (size_t)c * H) : Wg);
            dot1(wp, reinterpret_cast<const float4*>(g_co) + (size_t)b0 * H4,
                 H4, 8, lane, acc);
            const float bias = (c < MEL) ? bp[c] : bg[0];
#pragma unroll
            for (int bb = 0; bb < 8; ++bb) {
                float s = wsum(acc[bb]);
                if (lane == bb) {
                    const int b = b0 + bb;
                    const bool msk = step > lens[b];
                    if (c < MEL) {
                        const float val = s + bias;
                        g_decin[b * MEL + c] = val;
                        out[((size_t)b * TMEL + step) * MEL + c] = msk ? 0.f : val;
                    } else {
                        out[OFF_GATE + (size_t)b * TMEL + step] = msk ? 1000.f : (s + bias);
                    }
                }
            }
        }
        sbar(nblk, bx, ++gen);
    }
}

// ---------------- host launch -------------------------------------------------
extern "C" void kernel_launch(void* const* d_in, const int* in_sizes, int n_in,
                              void* d_out, int out_size) {
    (void)in_sizes; (void)n_in; (void)out_size;
    int dev = 0;
    cudaGetDevice(&dev);
    int sms = 0;
    cudaDeviceGetAttribute(&sms, cudaDevAttrMultiProcessorCount, dev);
    if (sms <= 0) sms = 148;
    if (sms > 152) sms = 152;
    sms &= ~1;                                // even block count (two halves)

    const int smem_bytes = 8192 * 16;         // 128 KB dynamic smem
    cudaFuncSetAttribute(decoder_kernel,
                         cudaFuncAttributeMaxDynamicSharedMemorySize, smem_bytes);

    decoder_kernel<<<sms, 512, smem_bytes>>>(
        (const float*)d_in[0],   // encoder_hidden [4,B,H]
        (const float*)d_in[1],   // encoder_outputs [B,TENC,H]
        (const int*)d_in[3],     // mel_spec_lens [B]   (d_in[2] = y, unused)
        (const float*)d_in[4],  (const float*)d_in[5],    // W_attn, b_attn
        (const float*)d_in[6],  (const float*)d_in[7],    // W_ih0, W_hh0
        (const float*)d_in[8],  (const float*)d_in[9],    // b_ih0, b_hh0
        (const float*)d_in[10], (const float*)d_in[11],   // W_ih1, W_hh1
        (const float*)d_in[12], (const float*)d_in[13],   // b_ih1, b_hh1
        (const float*)d_in[14], (const float*)d_in[15],   // Wc, bc
        (const float*)d_in[16], (const float*)d_in[17],   // Wp, bp
        (const float*)d_in[18], (const float*)d_in[19],   // Wg, bg
        (float*)d_out, sms);
}

// round 12
// speedup vs baseline: 1.2166x; 1.0001x over previous
#include <cuda_runtime.h>
#include <cuda_bf16.h>
#include <cstdint>

constexpr int B    = 32;
constexpr int H    = 1024;
constexpr int MEL  = 128;
constexpr int TENC = 512;
constexpr int TMEL = 400;
constexpr int H4   = H / 4;

constexpr size_t OFF_GATE = (size_t)B * TMEL * MEL;
constexpr size_t OFF_MASK = OFF_GATE + (size_t)B * TMEL;

// ---------------- device scratch (no allocations allowed) -------------------
__device__ float g_WT[(size_t)H * H];       // W_attn^T: g_WT[c*H+j] = W_attn[j*H+c]
__device__ float g_h0[2][B * H];
__device__ float g_h1[2][B * H];
__device__ float g_decin[B * MEL];
__device__ float g_v[B * H];
__device__ float g_scores[B * TENC];
__device__ float g_ctx[B * H];
__device__ float g_co[B * H];

// barriers
__device__ unsigned g_bar_arrive = 0;
__device__ volatile unsigned g_bar_gen = 0;
__device__ volatile unsigned g_arr[152 * 8];
__device__ volatile unsigned g_release;

// ---------------- helpers ----------------------------------------------------
__device__ __forceinline__ float wsum(float v) {
    v += __shfl_xor_sync(0xffffffffu, v, 16);
    v += __shfl_xor_sync(0xffffffffu, v, 8);
    v += __shfl_xor_sync(0xffffffffu, v, 4);
    v += __shfl_xor_sync(0xffffffffu, v, 2);
    v += __shfl_xor_sync(0xffffffffu, v, 1);
    return v;
}
__device__ __forceinline__ float wmax(float v) {
    v = fmaxf(v, __shfl_xor_sync(0xffffffffu, v, 16));
    v = fmaxf(v, __shfl_xor_sync(0xffffffffu, v, 8));
    v = fmaxf(v, __shfl_xor_sync(0xffffffffu, v, 4));
    v = fmaxf(v, __shfl_xor_sync(0xffffffffu, v, 2));
    v = fmaxf(v, __shfl_xor_sync(0xffffffffu, v, 1));
    return v;
}
__device__ __forceinline__ float dot4(float4 a, float4 b, float acc) {
    acc = fmaf(a.x, b.x, acc);
    acc = fmaf(a.y, b.y, acc);
    acc = fmaf(a.z, b.z, acc);
    acc = fmaf(a.w, b.w, acc);
    return acc;
}
__device__ __forceinline__ float sigmoidf_(float x) { return 1.f / (1.f + expf(-x)); }

// legacy atomic barrier (re-launch safe); used once after init
__device__ __forceinline__ void abar(int nblk) {
    __syncthreads();
    if (threadIdx.x == 0) {
        __threadfence();
        unsigned gen = g_bar_gen;
        if (atomicAdd(&g_bar_arrive, 1u) == (unsigned)nblk - 1u) {
            g_bar_arrive = 0;
            __threadfence();
            g_bar_gen = gen + 1u;
        } else {
            while (g_bar_gen == gen) { __nanosleep(64); }
        }
        __threadfence();
    }
    __syncthreads();
}

// grid barrier: per-block arrive slots, block 0 scans, all others poll one
// broadcast release word with backoff.
__device__ __forceinline__ void sbar(int nblk, int bx, unsigned gen) {
    __syncthreads();
    if (threadIdx.x == 0) { __threadfence(); g_arr[bx * 8] = gen; }
    if (bx == 0) {
        if (threadIdx.x < 32) {
            for (;;) {
                bool ok = true;
                for (int i = threadIdx.x; i < nblk; i += 32)
                    ok &= (g_arr[i * 8] >= gen);
                if (__all_sync(0xffffffffu, ok)) break;
                __nanosleep(32);
            }
            if (threadIdx.x == 0) { __threadfence(); g_release = gen; }
        }
    } else if (threadIdx.x == 0) {
        while (g_release < gen) { __nanosleep(64); }
        __threadfence();
    }
    __syncthreads();
}

// stage a half-batch activation slab into shared memory (coalesced float4)
__device__ __forceinline__ void stage(float4* dst, const float* src, int n4, int tid) {
    const float4* s = reinterpret_cast<const float4*>(src);
    for (int i = tid; i < n4; i += 512) dst[i] = s[i];
}

// 3-row dot vs 8 batches (acts in smem), weight prefetch depth 2.
// actb = smem base already offset to batch-group; bstride4 = per-batch stride (f4).
__device__ __forceinline__ void dot3(
    const float4* __restrict__ w0, const float4* __restrict__ w1,
    const float4* __restrict__ w2,
    const float4* __restrict__ actb, int bstride4, int nIt, int lane,
    float A0[8], float A1[8], float A2[8])
{
    float4 c0 = w0[lane], c1 = w1[lane], c2 = w2[lane];
    float4 n0 = c0, n1 = c1, n2 = c2;
    if (nIt > 1) { n0 = w0[lane + 32]; n1 = w1[lane + 32]; n2 = w2[lane + 32]; }
    for (int i = 0; i < nIt; ++i) {
        float4 p0 = n0, p1 = n1, p2 = n2;
        if (i + 2 < nIt) {
            p0 = w0[lane + (i + 2) * 32];
            p1 = w1[lane + (i + 2) * 32];
            p2 = w2[lane + (i + 2) * 32];
        }
        const float4* a = actb + i * 32 + lane;
#pragma unroll
        for (int bb = 0; bb < 8; ++bb) {
            float4 av = a[bb * bstride4];
            A0[bb] = dot4(c0, av, A0[bb]);
            A1[bb] = dot4(c1, av, A1[bb]);
            A2[bb] = dot4(c2, av, A2[bb]);
        }
        c0 = n0; c1 = n1; c2 = n2;
        n0 = p0; n1 = p1; n2 = p2;
    }
}

// 1-row dot vs 8 batches, prefetch depth 2 (acts smem or global).
__device__ __forceinline__ void dot1(
    const float4* __restrict__ w,
    const float4* __restrict__ actb, int bstride4, int nIt, int lane,
    float A[8])
{
    float4 c = w[lane];
    float4 n = c;
    if (nIt > 1) n = w[lane + 32];
    for (int i = 0; i < nIt; ++i) {
        float4 p = n;
        if (i + 2 < nIt) p = w[lane + (i + 2) * 32];
        const float4* a = actb + i * 32 + lane;
#pragma unroll
        for (int bb = 0; bb < 8; ++bb)
            A[bb] = dot4(c, a[bb * bstride4], A[bb]);
        c = n; n = p;
    }
}

// merged GRU cell: acts from smem, direct state write
__device__ __forceinline__ void gru_sm(
    int j, int bl0, int lane, int hb0,
    const float4* __restrict__ smX, int XD,
    const float4* __restrict__ smH, const float* __restrict__ smHf,
    float* __restrict__ hnew,
    const float* __restrict__ Wih, const float* __restrict__ Whh,
    const float* __restrict__ bih, const float* __restrict__ bhh)
{
    const int XD4 = XD >> 2, nItX = XD4 >> 5;
    float ar[8], az[8], ani[8], anh[8];
#pragma unroll
    for (int i = 0; i < 8; ++i) { ar[i] = 0.f; az[i] = 0.f; ani[i] = 0.f; anh[i] = 0.f; }

    dot3(reinterpret_cast<const float4*>(Wih + (size_t)j * XD),
         reinterpret_cast<const float4*>(Wih + (size_t)(H + j) * XD),
         reinterpret_cast<const float4*>(Wih + (size_t)(2 * H + j) * XD),
         smX + bl0 * XD4, XD4, nItX, lane, ar, az, ani);
    dot3(reinterpret_cast<const float4*>(Whh + (size_t)j * H),
         reinterpret_cast<const float4*>(Whh + (size_t)(H + j) * H),
         reinterpret_cast<const float4*>(Whh + (size_t)(2 * H + j) * H),
         smH + bl0 * H4, H4, 8, lane, ar, az, anh);

    const float br  = bih[j] + bhh[j];
    const float bz  = bih[H + j] + bhh[H + j];
    const float bni = bih[2 * H + j];
    const float bnh = bhh[2 * H + j];
#pragma unroll
    for (int bb = 0; bb < 8; ++bb) {
        float r  = wsum(ar[bb]);
        float z  = wsum(az[bb]);
        float ni = wsum(ani[bb]);
        float nh = wsum(anh[bb]);
        if (lane == bb) {
            float rr = sigmoidf_(r + br);
            float zz = sigmoidf_(z + bz);
            float hp = smHf[(bl0 + bb) * H + j];
            float nn = tanhf(ni + bni + rr * (nh + bnh));
            hnew[(hb0 + bl0 + bb) * H + j] = (1.f - zz) * nn + zz * hp;
        }
    }
}

// ---------------- main persistent kernel -------------------------------------
__global__ void __launch_bounds__(512, 1)
decoder_kernel(const float* __restrict__ enc_hidden,
               const float* __restrict__ enc_out,
               const int*   __restrict__ lens,
               const float* __restrict__ W_attn, const float* __restrict__ b_attn,
               const float* __restrict__ Wih0, const float* __restrict__ Whh0,
               const float* __restrict__ bih0, const float* __restrict__ bhh0,
               const float* __restrict__ Wih1, const float* __restrict__ Whh1,
               const float* __restrict__ bih1, const float* __restrict__ bhh1,
               const float* __restrict__ Wc,   const float* __restrict__ bc,
               const float* __restrict__ Wp,   const float* __restrict__ bp,
               const float* __restrict__ Wg,   const float* __restrict__ bg,
               float* __restrict__ out, int nblk) {
    extern __shared__ float4 sm4[];
    float4* smA = sm4;                 // 4096 f4 (64 KB)
    float4* smB = sm4 + 4096;          // 4096 f4 (64 KB)
    const float* smAf = reinterpret_cast<const float*>(smA);
    const float* smBf = reinterpret_cast<const float*>(smB);

    const int tid  = threadIdx.x;
    const int lane = tid & 31;
    const int wid  = tid >> 5;
    const int bx   = blockIdx.x;
    // half mapping: block owns one 16-batch half; acts staged in smem.
    const int half = bx & 1;
    const int bq   = bx >> 1;
    const int nbh  = nblk >> 1;
    const int wq   = bq * 16 + wid;     // warp index within half
    const int NWQ  = nbh * 16;          // warps per half
    const int hb0  = half * 16;         // first batch of half
    const int gtid = bx * blockDim.x + tid;
    const int gsz  = nblk * blockDim.x;

    // ================= init =================
    for (int i = gtid; i < H * H; i += gsz) {
        int c = i >> 10, j = i & (H - 1);
        g_WT[i] = W_attn[(size_t)j * H + c];
    }
    for (int i = gtid; i < B * H; i += gsz) {
        g_h0[0][i] = enc_hidden[i];
        g_h1[0][i] = enc_hidden[B * H + i];
    }
    for (int i = gtid; i < B * MEL; i += gsz) g_decin[i] = 0.f;
    for (int i = gtid; i < B * TMEL; i += gsz) {
        int b = i / TMEL, t = i - b * TMEL;
        out[OFF_MASK + i] = (t > lens[b]) ? 1.f : 0.f;
    }
    for (int i = gtid; i < 152 * 8; i += gsz) g_arr[i] = 0u;
    if (gtid == 0) g_release = 0u;
    abar(nblk);

    unsigned gen = 0;

    // ================= 400 autoregressive steps =================
    for (int step = 0; step < TMEL; ++step) {
        const int cur = step & 1, nxt = cur ^ 1;

        // ---- GRU layer 0 (x = decin in smA, h = h0[cur] in smB) ----
        stage(smA, g_decin + hb0 * MEL, 16 * MEL / 4, tid);
        stage(smB, g_h0[cur] + hb0 * H, 4096, tid);
        __syncthreads();
        for (int job = wq; job < 2048; job += NWQ)
            gru_sm(job >> 1, (job & 1) * 8, lane, hb0, smA, MEL, smB, smBf,
                   g_h0[nxt], Wih0, Whh0, bih0, bhh0);
        sbar(nblk, bx, ++gen);

        // ---- GRU layer 1 (x = h0[nxt] in smA, h = h1[cur] in smB) ----
        stage(smA, g_h0[nxt] + hb0 * H, 4096, tid);
        stage(smB, g_h1[cur] + hb0 * H, 4096, tid);
        __syncthreads();
        for (int job = wq; job < 2048; job += NWQ)
            gru_sm(job >> 1, (job & 1) * 8, lane, hb0, smA, H, smB, smBf,
                   g_h1[nxt], Wih1, Whh1, bih1, bhh1);
        sbar(nblk, bx, ++gen);

        // ---- Pv: v[b,c] = sum_j h1[b,j] * W_attn[j,c] (bias drops in softmax) ----
        stage(smA, g_h1[nxt] + hb0 * H, 4096, tid);
        __syncthreads();
        for (int job = wq; job < 2048; job += NWQ) {
            const int c   = job >> 1;
            const int bl0 = (job & 1) * 8;
            float acc[8];
#pragma unroll
            for (int i = 0; i < 8; ++i) acc[i] = 0.f;
            dot1(reinterpret_cast<const float4*>(g_WT + (size_t)c * H),
                 smA + bl0 * H4, H4, 8, lane, acc);
#pragma unroll
            for (int bb = 0; bb < 8; ++bb) {
                float s = wsum(acc[bb]);
                if (lane == bb) g_v[(hb0 + bl0 + bb) * H + c] = s;
            }
        }
        sbar(nblk, bx, ++gen);

        // ---- P3: scores[b,t] = v[b,:] . enc_out[b,t,:]  (1024 jobs/half) ----
        stage(smA, g_v + hb0 * H, 4096, tid);
        __syncthreads();
        for (int job = wq; job < 1024; job += NWQ) {
            const int bl = job >> 6;
            const int b  = hb0 + bl;
            const int t0 = (job & 63) * 8;
            float acc[8];
#pragma unroll
            for (int i = 0; i < 8; ++i) acc[i] = 0.f;
            const float4* vb = smA + bl * H4;
            const float4* Eb = reinterpret_cast<const float4*>(
                enc_out + ((size_t)b * TENC + t0) * H);
            for (int k = lane; k < H4; k += 32) {
                float4 vv = vb[k];
#pragma unroll
                for (int t = 0; t < 8; ++t) {
                    float4 ev = Eb[(size_t)t * H4 + k];
                    acc[t] = fmaf(vv.x, ev.x, fmaf(vv.y, ev.y,
                             fmaf(vv.z, ev.z, fmaf(vv.w, ev.w, acc[t]))));
                }
            }
#pragma unroll
            for (int t = 0; t < 8; ++t) {
                float s = wsum(acc[t]);
                if (lane == t) g_scores[b * TENC + t0 + t] = s;
            }
        }
        sbar(nblk, bx, ++gen);

        // ---- P4: softmax (per-warp) + context (512 jobs/half) ----
        for (int job = wq; job < 512; job += NWQ) {
            const int b  = hb0 + (job >> 5);
            const int hg = (job & 31) * 32;
            const float* srow = g_scores + b * TENC;
            float sc[16];
            float mx = -1e30f;
#pragma unroll
            for (int i = 0; i < 16; ++i) {
                sc[i] = srow[i * 32 + lane];
                mx = fmaxf(mx, sc[i]);
            }
            mx = wmax(mx);
            float sm = 0.f;
#pragma unroll
            for (int i = 0; i < 16; ++i) { sc[i] = expf(sc[i] - mx); sm += sc[i]; }
            sm = wsum(sm);
            const float inv = 1.f / sm;

            float acc0 = 0.f, acc1 = 0.f;
            const float* ep = enc_out + (size_t)b * TENC * H + hg + lane;
#pragma unroll
            for (int i = 0; i < 8; ++i) {
                float pv0 = sc[i] * inv;
                float pv1 = sc[i + 8] * inv;
#pragma unroll 8
                for (int tt = 0; tt < 32; ++tt) {
                    float p0 = __shfl_sync(0xffffffffu, pv0, tt);
                    float p1 = __shfl_sync(0xffffffffu, pv1, tt);
                    float e0 = ep[(size_t)(i * 32 + tt) * H];
                    float e1 = ep[(size_t)((i + 8) * 32 + tt) * H];
                    acc0 = fmaf(p0, e0, acc0);
                    acc1 = fmaf(p1, e1, acc1);
                }
            }
            g_ctx[(size_t)b * H + hg + lane] = acc0 + acc1;
        }
        sbar(nblk, bx, ++gen);

        // ---- P5: co = tanh([h1; ctx] @ Wc^T + bc) (h1 in smA, ctx in smB) ----
        stage(smA, g_h1[nxt] + hb0 * H, 4096, tid);
        stage(smB, g_ctx + hb0 * H, 4096, tid);
        __syncthreads();
        for (int job = wq; job < 2048; job += NWQ) {
            const int j   = job >> 1;
            const int bl0 = (job & 1) * 8;
            float acc[8];
#pragma unroll
            for (int i = 0; i < 8; ++i) acc[i] = 0.f;
            dot1(reinterpret_cast<const float4*>(Wc + (size_t)j * 2 * H),
                 smA + bl0 * H4, H4, 8, lane, acc);
            dot1(reinterpret_cast<const float4*>(Wc + (size_t)j * 2 * H) + H4,
                 smB + bl0 * H4, H4, 8, lane, acc);
            const float bcv = bc[j];
#pragma unroll
            for (int bb = 0; bb < 8; ++bb) {
                float s = wsum(acc[bb]);
                if (lane == bb) g_co[(hb0 + bl0 + bb) * H + j] = tanhf(s + bcv);
            }
        }
        sbar(nblk, bx, ++gen);

        // ---- P6: mel + gate projections (258 jobs/half, co from L2) ----
        for (int job = wq; job < 258; job += NWQ) {
            const int c   = job >> 1;
            const int bl0 = (job & 1) * 8;
            const int b0  = hb0 + bl0;
            float acc[8];
#pragma unroll
            for (int i = 0; i < 8; ++i) acc[i] = 0.f;
            const float4* wp = reinterpret_cast<const float4*>(
                (c < MEL) ? (Wp + (size_t)c * H) : Wg);
            dot1(wp, reinterpret_cast<const float4*>(g_co) + (size_t)b0 * H4,
                 H4, 8, lane, acc);
            const float bias = (c < MEL) ? bp[c] : bg[0];
#pragma unroll
            for (int bb = 0; bb < 8; ++bb) {
                float s = wsum(acc[bb]);
                if (lane == bb) {
                    const int b = b0 + bb;
                    const bool msk = step > lens[b];
                    if (c < MEL) {
                        const float val = s + bias;
                        g_decin[b * MEL + c] = val;
                        out[((size_t)b * TMEL + step) * MEL + c] = msk ? 0.f : val;
                    } else {
                        out[OFF_GATE + (size_t)b * TMEL + step] = msk ? 1000.f : (s + bias);
                    }
                }
            }
        }
        sbar(nblk, bx, ++gen);
    }
}

// ---------------- host launch -------------------------------------------------
extern "C" void kernel_launch(void* const* d_in, const int* in_sizes, int n_in,
                              void* d_out, int out_size) {
    (void)in_sizes; (void)n_in; (void)out_size;
    int dev = 0;
    cudaGetDevice(&dev);
    int sms = 0;
    cudaDeviceGetAttribute(&sms, cudaDevAttrMultiProcessorCount, dev);
    if (sms <= 0) sms = 148;
    if (sms > 152) sms = 152;
    sms &= ~1;                                // even block count (two halves)

    const int smem_bytes = 8192 * 16;         // 128 KB dynamic smem
    cudaFuncSetAttribute(decoder_kernel,
                         cudaFuncAttributeMaxDynamicSharedMemorySize, smem_bytes);

    decoder_kernel<<<sms, 512, smem_bytes>>>(
        (const float*)d_in[0],   // encoder_hidden [4,B,H]
        (const float*)d_in[1],   // encoder_outputs [B,TENC,H]
        (const int*)d_in[3],     // mel_spec_lens [B]   (d_in[2] = y, unused)
        (const float*)d_in[4],  (const float*)d_in[5],    // W_attn, b_attn
        (const float*)d_in[6],  (const float*)d_in[7],    // W_ih0, W_hh0
        (const float*)d_in[8],  (const float*)d_in[9],    // b_ih0, b_hh0
        (const float*)d_in[10], (const float*)d_in[11],   // W_ih1, W_hh1
        (const float*)d_in[12], (const float*)d_in[13],   // b_ih1, b_hh1
        (const float*)d_in[14], (const float*)d_in[15],   // Wc, bc
        (const float*)d_in[16], (const float*)d_in[17],   // Wp, bp
        (const float*)d_in[18], (const float*)d_in[19],   // Wg, bg
        (float*)d_out, sms);
}

// round 13
// speedup vs baseline: 1.5746x; 1.2943x over previous
#include <cuda_runtime.h>
#include <cuda_bf16.h>
#include <cstdint>

constexpr int B    = 32;
constexpr int H    = 1024;
constexpr int MEL  = 128;
constexpr int TENC = 512;
constexpr int TMEL = 400;
constexpr int H4   = H / 4;

constexpr size_t OFF_GATE = (size_t)B * TMEL * MEL;
constexpr size_t OFF_MASK = OFF_GATE + (size_t)B * TMEL;

// ---------------- device scratch (no allocations allowed) -------------------
__device__ float g_WT[(size_t)H * H];       // W_attn^T
__device__ float g_h0[2][B * H];
__device__ float g_h1[2][B * H];
__device__ float g_decin[B * MEL];
__device__ float g_v[B * H];
__device__ float g_co[B * H];
// attention partials: 4 t-tiles of 128
__device__ float pm[4][B];
__device__ float pl[4][B];
__device__ float pctx[4][B * H];

// barriers
__device__ unsigned g_bar_arrive = 0;
__device__ volatile unsigned g_bar_gen = 0;
__device__ volatile unsigned g_arr[152 * 8];
__device__ volatile unsigned g_release;

// ---------------- helpers ----------------------------------------------------
__device__ __forceinline__ float wsum(float v) {
    v += __shfl_xor_sync(0xffffffffu, v, 16);
    v += __shfl_xor_sync(0xffffffffu, v, 8);
    v += __shfl_xor_sync(0xffffffffu, v, 4);
    v += __shfl_xor_sync(0xffffffffu, v, 2);
    v += __shfl_xor_sync(0xffffffffu, v, 1);
    return v;
}
__device__ __forceinline__ float dot4(float4 a, float4 b, float acc) {
    acc = fmaf(a.x, b.x, acc);
    acc = fmaf(a.y, b.y, acc);
    acc = fmaf(a.z, b.z, acc);
    acc = fmaf(a.w, b.w, acc);
    return acc;
}
__device__ __forceinline__ float sigmoidf_(float x) { return 1.f / (1.f + expf(-x)); }

__device__ __forceinline__ void abar(int nblk) {
    __syncthreads();
    if (threadIdx.x == 0) {
        __threadfence();
        unsigned gen = g_bar_gen;
        if (atomicAdd(&g_bar_arrive, 1u) == (unsigned)nblk - 1u) {
            g_bar_arrive = 0;
            __threadfence();
            g_bar_gen = gen + 1u;
        } else {
            while (g_bar_gen == gen) { __nanosleep(64); }
        }
        __threadfence();
    }
    __syncthreads();
}

// grid barrier: per-block arrive slots, block 0 scans, others poll one word.
__device__ __forceinline__ void sbar(int nblk, int bx, unsigned gen) {
    __syncthreads();
    if (threadIdx.x == 0) { __threadfence(); g_arr[bx * 8] = gen; }
    if (bx == 0) {
        if (threadIdx.x < 32) {
            for (;;) {
                bool ok = true;
                for (int i = threadIdx.x; i < nblk; i += 32)
                    ok &= (g_arr[i * 8] >= gen);
                if (__all_sync(0xffffffffu, ok)) break;
                __nanosleep(32);
            }
            if (threadIdx.x == 0) { __threadfence(); g_release = gen; }
        }
    } else if (threadIdx.x == 0) {
        while (g_release < gen) { __nanosleep(64); }
        __threadfence();
    }
    __syncthreads();
}

__device__ __forceinline__ void stage(float4* dst, const float* src, int n4, int tid) {
    const float4* s = reinterpret_cast<const float4*>(src);
    for (int i = tid; i < n4; i += 512) dst[i] = s[i];
}

// 3-row dot vs 8 batches (acts in smem), weight prefetch depth 2.
__device__ __forceinline__ void dot3(
    const float4* __restrict__ w0, const float4* __restrict__ w1,
    const float4* __restrict__ w2,
    const float4* __restrict__ actb, int bstride4, int nIt, int lane,
    float A0[8], float A1[8], float A2[8])
{
    float4 c0 = w0[lane], c1 = w1[lane], c2 = w2[lane];
    float4 n0 = c0, n1 = c1, n2 = c2;
    if (nIt > 1) { n0 = w0[lane + 32]; n1 = w1[lane + 32]; n2 = w2[lane + 32]; }
    for (int i = 0; i < nIt; ++i) {
        float4 p0 = n0, p1 = n1, p2 = n2;
        if (i + 2 < nIt) {
            p0 = w0[lane + (i + 2) * 32];
            p1 = w1[lane + (i + 2) * 32];
            p2 = w2[lane + (i + 2) * 32];
        }
        const float4* a = actb + i * 32 + lane;
#pragma unroll
        for (int bb = 0; bb < 8; ++bb) {
            float4 av = a[bb * bstride4];
            A0[bb] = dot4(c0, av, A0[bb]);
            A1[bb] = dot4(c1, av, A1[bb]);
            A2[bb] = dot4(c2, av, A2[bb]);
        }
        c0 = n0; c1 = n1; c2 = n2;
        n0 = p0; n1 = p1; n2 = p2;
    }
}

// 1-row dot vs 8 batches, prefetch depth 2.
__device__ __forceinline__ void dot1(
    const float4* __restrict__ w,
    const float4* __restrict__ actb, int bstride4, int nIt, int lane,
    float A[8])
{
    float4 c = w[lane];
    float4 n = c;
    if (nIt > 1) n = w[lane + 32];
    for (int i = 0; i < nIt; ++i) {
        float4 p = n;
        if (i + 2 < nIt) p = w[lane + (i + 2) * 32];
        const float4* a = actb + i * 32 + lane;
#pragma unroll
        for (int bb = 0; bb < 8; ++bb)
            A[bb] = dot4(c, a[bb * bstride4], A[bb]);
        c = n; n = p;
    }
}

// merged GRU cell: acts from smem, direct state write
__device__ __forceinline__ void gru_sm(
    int j, int bl0, int lane, int hb0,
    const float4* __restrict__ smX, int XD,
    const float4* __restrict__ smH, const float* __restrict__ smHf,
    float* __restrict__ hnew,
    const float* __restrict__ Wih, const float* __restrict__ Whh,
    const float* __restrict__ bih, const float* __restrict__ bhh)
{
    const int XD4 = XD >> 2, nItX = XD4 >> 5;
    float ar[8], az[8], ani[8], anh[8];
#pragma unroll
    for (int i = 0; i < 8; ++i) { ar[i] = 0.f; az[i] = 0.f; ani[i] = 0.f; anh[i] = 0.f; }

    dot3(reinterpret_cast<const float4*>(Wih + (size_t)j * XD),
         reinterpret_cast<const float4*>(Wih + (size_t)(H + j) * XD),
         reinterpret_cast<const float4*>(Wih + (size_t)(2 * H + j) * XD),
         smX + bl0 * XD4, XD4, nItX, lane, ar, az, ani);
    dot3(reinterpret_cast<const float4*>(Whh + (size_t)j * H),
         reinterpret_cast<const float4*>(Whh + (size_t)(H + j) * H),
         reinterpret_cast<const float4*>(Whh + (size_t)(2 * H + j) * H),
         smH + bl0 * H4, H4, 8, lane, ar, az, anh);

    const float br  = bih[j] + bhh[j];
    const float bz  = bih[H + j] + bhh[H + j];
    const float bni = bih[2 * H + j];
    const float bnh = bhh[2 * H + j];
#pragma unroll
    for (int bb = 0; bb < 8; ++bb) {
        float r  = wsum(ar[bb]);
        float z  = wsum(az[bb]);
        float ni = wsum(ani[bb]);
        float nh = wsum(anh[bb]);
        if (lane == bb) {
            float rr = sigmoidf_(r + br);
            float zz = sigmoidf_(z + bz);
            float hp = smHf[(bl0 + bb) * H + j];
            float nn = tanhf(ni + bni + rr * (nh + bnh));
            hnew[(hb0 + bl0 + bb) * H + j] = (1.f - zz) * nn + zz * hp;
        }
    }
}

// ---------------- main persistent kernel -------------------------------------
__global__ void __launch_bounds__(512, 1)
decoder_kernel(const float* __restrict__ enc_hidden,
               const float* __restrict__ enc_out,
               const int*   __restrict__ lens,
               const float* __restrict__ W_attn, const float* __restrict__ b_attn,
               const float* __restrict__ Wih0, const float* __restrict__ Whh0,
               const float* __restrict__ bih0, const float* __restrict__ bhh0,
               const float* __restrict__ Wih1, const float* __restrict__ Whh1,
               const float* __restrict__ bih1, const float* __restrict__ bhh1,
               const float* __restrict__ Wc,   const float* __restrict__ bc,
               const float* __restrict__ Wp,   const float* __restrict__ bp,
               const float* __restrict__ Wg,   const float* __restrict__ bg,
               float* __restrict__ out, int nblk) {
    extern __shared__ float4 sm4[];
    float4* smA = sm4;                 // 64 KB
    float4* smB = sm4 + 4096;          // 64 KB
    const float* smBf = reinterpret_cast<const float*>(smB);
    float* smV = reinterpret_cast<float*>(sm4);   // ATT: v[b] (4 KB)

    __shared__ float smS[16];          // subtile scores
    __shared__ float smP[16];          // subtile exp weights
    __shared__ float smW[64];          // per-batch combine weights (4 tiles x 16)

    const int tid  = threadIdx.x;
    const int lane = tid & 31;
    const int wid  = tid >> 5;
    const int bx   = blockIdx.x;
    const int half = bx & 1;
    const int bq   = bx >> 1;
    const int nbh  = nblk >> 1;
    const int wq   = bq * 16 + wid;
    const int NWQ  = nbh * 16;
    const int hb0  = half * 16;
    const int gtid = bx * blockDim.x + tid;
    const int gsz  = nblk * blockDim.x;

    // ================= init =================
    for (int i = gtid; i < H * H; i += gsz) {
        int c = i >> 10, j = i & (H - 1);
        g_WT[i] = W_attn[(size_t)j * H + c];
    }
    for (int i = gtid; i < B * H; i += gsz) {
        g_h0[0][i] = enc_hidden[i];
        g_h1[0][i] = enc_hidden[B * H + i];
    }
    for (int i = gtid; i < B * MEL; i += gsz) g_decin[i] = 0.f;
    for (int i = gtid; i < B * TMEL; i += gsz) {
        int b = i / TMEL, t = i - b * TMEL;
        out[OFF_MASK + i] = (t > lens[b]) ? 1.f : 0.f;
    }
    for (int i = gtid; i < 152 * 8; i += gsz) g_arr[i] = 0u;
    if (gtid == 0) g_release = 0u;
    abar(nblk);

    unsigned gen = 0;

    // ================= 400 autoregressive steps =================
    for (int step = 0; step < TMEL; ++step) {
        const int cur = step & 1, nxt = cur ^ 1;

        // ---- GRU layer 0 ----
        stage(smA, g_decin + hb0 * MEL, 16 * MEL / 4, tid);
        stage(smB, g_h0[cur] + hb0 * H, 4096, tid);
        __syncthreads();
        for (int job = wq; job < 2048; job += NWQ)
            gru_sm(job >> 1, (job & 1) * 8, lane, hb0, smA, MEL, smB, smBf,
                   g_h0[nxt], Wih0, Whh0, bih0, bhh0);
        sbar(nblk, bx, ++gen);

        // ---- GRU layer 1 ----
        stage(smA, g_h0[nxt] + hb0 * H, 4096, tid);
        stage(smB, g_h1[cur] + hb0 * H, 4096, tid);
        __syncthreads();
        for (int job = wq; job < 2048; job += NWQ)
            gru_sm(job >> 1, (job & 1) * 8, lane, hb0, smA, H, smB, smBf,
                   g_h1[nxt], Wih1, Whh1, bih1, bhh1);
        sbar(nblk, bx, ++gen);

        // ---- Pv: v = W_attn^T h1 (bias drops in softmax) ----
        stage(smA, g_h1[nxt] + hb0 * H, 4096, tid);
        __syncthreads();
        for (int job = wq; job < 2048; job += NWQ) {
            const int c   = job >> 1;
            const int bl0 = (job & 1) * 8;
            float acc[8];
#pragma unroll
            for (int i = 0; i < 8; ++i) acc[i] = 0.f;
            dot1(reinterpret_cast<const float4*>(g_WT + (size_t)c * H),
                 smA + bl0 * H4, H4, 8, lane, acc);
#pragma unroll
            for (int bb = 0; bb < 8; ++bb) {
                float s = wsum(acc[bb]);
                if (lane == bb) g_v[(hb0 + bl0 + bb) * H + c] = s;
            }
        }
        sbar(nblk, bx, ++gen);

        // ---- ATT: fused scores+softmax+context, enc read ONCE (streamed) ----
        // job = (batch, 128-t tile) = 128 block-jobs; 16-t subtiles (64 KB, L1)
        for (int job = bx; job < 128; job += nblk) {
            const int b    = job >> 2;
            const int tile = job & 3;
            const int t0   = tile * 128;
            __syncthreads();
            for (int i = tid; i < 1024; i += 512) smV[i] = g_v[b * H + i];
            __syncthreads();

            float m_run = -1e30f, l_run = 0.f;
            float a0 = 0.f, a1 = 0.f;
            const int hc = wid * 64;

            for (int sub = 0; sub < 8; ++sub) {
                const int ts = t0 + sub * 16;
                // scores: warp wid computes t = ts + wid
                {
                    const float4* er = reinterpret_cast<const float4*>(
                        enc_out + ((size_t)b * TENC + ts + wid) * H);
                    const float4* v4 = reinterpret_cast<const float4*>(smV);
                    float acc = 0.f;
#pragma unroll
                    for (int k = 0; k < 8; ++k) {
                        float4 ev = __ldcs(er + k * 32 + lane);
                        acc = dot4(v4[k * 32 + lane], ev, acc);
                    }
                    acc = wsum(acc);
                    if (lane == 0) smS[wid] = acc;
                }
                __syncthreads();
                float msub = -1e30f;
#pragma unroll
                for (int i = 0; i < 16; ++i) msub = fmaxf(msub, smS[i]);
                const float m_new = fmaxf(m_run, msub);
                if (lane == 0) smP[wid] = expf(smS[wid] - m_new);
                const float scale = expf(m_run - m_new);
                __syncthreads();
                // context accumulate for this warp's 64-wide h-chunk
                a0 *= scale; a1 *= scale;
                float lsub = 0.f;
                const float* eb = enc_out + ((size_t)b * TENC + ts) * H + hc + lane;
#pragma unroll 4
                for (int t = 0; t < 16; ++t) {
                    float p = smP[t];
                    lsub += p;
                    a0 = fmaf(p, __ldcs(eb + (size_t)t * H), a0);
                    a1 = fmaf(p, __ldcs(eb + (size_t)t * H + 32), a1);
                }
                l_run = l_run * scale + lsub;
                m_run = m_new;
                __syncthreads();
            }
            // write tile partials (unnormalized)
            pctx[tile][b * H + hc + lane]      = a0;
            pctx[tile][b * H + hc + 32 + lane] = a1;
            if (tid == 0) { pm[tile][b] = m_run; pl[tile][b] = l_run; }
        }
        sbar(nblk, bx, ++gen);

        const float* h1n = g_h1[nxt];

        // ---- P5: combine ctx tiles into smB, stage h1 into smA, then GEMM ----
        if (tid < 16) {
            const int b = hb0 + tid;
            float m0 = pm[0][b], m1 = pm[1][b], m2 = pm[2][b], m3 = pm[3][b];
            float M = fmaxf(fmaxf(m0, m1), fmaxf(m2, m3));
            float e0 = expf(m0 - M), e1 = expf(m1 - M);
            float e2 = expf(m2 - M), e3 = expf(m3 - M);
            float invL = 1.f / (e0 * pl[0][b] + e1 * pl[1][b] +
                                e2 * pl[2][b] + e3 * pl[3][b]);
            smW[tid]      = e0 * invL;
            smW[16 + tid] = e1 * invL;
            smW[32 + tid] = e2 * invL;
            smW[48 + tid] = e3 * invL;
        }
        stage(smA, h1n + hb0 * H, 4096, tid);
        __syncthreads();
        for (int i = tid; i < 4096; i += 512) {
            const int bl = i >> 8;
            const size_t off = (size_t)(hb0 + bl) * 256 + (i & 255);
            float w0 = smW[bl], w1 = smW[16 + bl], w2 = smW[32 + bl], w3 = smW[48 + bl];
            float4 c0 = reinterpret_cast<const float4*>(pctx[0])[off];
            float4 c1 = reinterpret_cast<const float4*>(pctx[1])[off];
            float4 c2 = reinterpret_cast<const float4*>(pctx[2])[off];
            float4 c3 = reinterpret_cast<const float4*>(pctx[3])[off];
            float4 r;
            r.x = w0 * c0.x + w1 * c1.x + w2 * c2.x + w3 * c3.x;
            r.y = w0 * c0.y + w1 * c1.y + w2 * c2.y + w3 * c3.y;
            r.z = w0 * c0.z + w1 * c1.z + w2 * c2.z + w3 * c3.z;
            r.w = w0 * c0.w + w1 * c1.w + w2 * c2.w + w3 * c3.w;
            smB[i] = r;
        }
        __syncthreads();
        for (int job = wq; job < 2048; job += NWQ) {
            const int j   = job >> 1;
            const int bl0 = (job & 1) * 8;
            float acc[8];
#pragma unroll
            for (int i = 0; i < 8; ++i) acc[i] = 0.f;
            dot1(reinterpret_cast<const float4*>(Wc + (size_t)j * 2 * H),
                 smA + bl0 * H4, H4, 8, lane, acc);
            dot1(reinterpret_cast<const float4*>(Wc + (size_t)j * 2 * H) + H4,
                 smB + bl0 * H4, H4, 8, lane, acc);
            const float bcv = bc[j];
#pragma unroll
            for (int bb = 0; bb < 8; ++bb) {
                float s = wsum(acc[bb]);
                if (lane == bb) g_co[(hb0 + bl0 + bb) * H + j] = tanhf(s + bcv);
            }
        }
        sbar(nblk, bx, ++gen);

        // ---- P6: mel + gate projections ----
        for (int job = wq; job < 258; job += NWQ) {
            const int c   = job >> 1;
            const int bl0 = (job & 1) * 8;
            const int b0  = hb0 + bl0;
            float acc[8];
#pragma unroll
            for (int i = 0; i < 8; ++i) acc[i] = 0.f;
            const float4* wp = reinterpret_cast<const float4*>(
                (c < MEL) ? (Wp + (size_t)c * H) : Wg);
            dot1(wp, reinterpret_cast<const float4*>(g_co) + (size_t)b0 * H4,
                 H4, 8, lane, acc);
            const float bias = (c < MEL) ? bp[c] : bg[0];
#pragma unroll
            for (int bb = 0; bb < 8; ++bb) {
                float s = wsum(acc[bb]);
                if (lane == bb) {
                    const int b = b0 + bb;
                    const bool msk = step > lens[b];
                    if (c < MEL) {
                        const float val = s + bias;
                        g_decin[b * MEL + c] = val;
                        __stcs(&out[((size_t)b * TMEL + step) * MEL + c], msk ? 0.f : val);
                    } else {
                        __stcs(&out[OFF_GATE + (size_t)b * TMEL + step],
                               msk ? 1000.f : (s + bias));
                    }
                }
            }
        }
        sbar(nblk, bx, ++gen);
    }
}

// ---------------- host launch -------------------------------------------------
extern "C" void kernel_launch(void* const* d_in, const int* in_sizes, int n_in,
                              void* d_out, int out_size) {
    (void)in_sizes; (void)n_in; (void)out_size;
    int dev = 0;
    cudaGetDevice(&dev);
    int sms = 0;
    cudaDeviceGetAttribute(&sms, cudaDevAttrMultiProcessorCount, dev);
    if (sms <= 0) sms = 148;
    if (sms > 152) sms = 152;
    sms &= ~1;

    const int smem_bytes = 8192 * 16;         // 128 KB dynamic smem
    cudaFuncSetAttribute(decoder_kernel,
                         cudaFuncAttributeMaxDynamicSharedMemorySize, smem_bytes);

    decoder_kernel<<<sms, 512, smem_bytes>>>(
        (const float*)d_in[0],   // encoder_hidden [4,B,H]
        (const float*)d_in[1],   // encoder_outputs [B,TENC,H]
        (const int*)d_in[3],     // mel_spec_lens [B]   (d_in[2] = y, unused)
        (const float*)d_in[4],  (const float*)d_in[5],    // W_attn, b_attn
        (const float*)d_in[6],  (const float*)d_in[7],    // W_ih0, W_hh0
        (const float*)d_in[8],  (const float*)d_in[9],    // b_ih0, b_hh0
        (const float*)d_in[10], (const float*)d_in[11],   // W_ih1, W_hh1
        (const float*)d_in[12], (const float*)d_in[13],   // b_ih1, b_hh1
        (const float*)d_in[14], (const float*)d_in[15],   // Wc, bc
        (const float*)d_in[16], (const float*)d_in[17],   // Wp, bp
        (const float*)d_in[18], (const float*)d_in[19],   // Wg, bg
        (float*)d_out, sms);
}